// round 4
// baseline (speedup 1.0000x reference)
#include <cuda_runtime.h>
#include <cstdint>

#define NN 100000
#define DD 16
#define EE 3200000
#define N2 (2 * NN)                    // combined counter space (both layers)
#define SCAN_TB 512
#define NBA ((N2 + SCAN_TB - 1) / SCAN_TB)   // 391 scanA blocks

// ---- scratch (device globals; allocation is forbidden) ----
__device__ float g_fs1[NN * DD];
__device__ float g_fd1[NN * DD];
__device__ float g_fs2[NN * DD];
__device__ float g_fd2[NN * DD];
__device__ int   g_cnt[N2];
__device__ int   g_off[N2 + 1];
__device__ int   g_pos[N2];
__device__ int   g_bsum[SCAN_TB];
__device__ int   g_bpre[SCAN_TB];
__device__ int   g_eidx[2 * EE];

__device__ __forceinline__ float lrelu(float x, float s) {
    return x >= 0.f ? x : s * x;
}

// ---------------------------------------------------------------------------
// CSR build (both graphs at once)
// ---------------------------------------------------------------------------
__global__ __launch_bounds__(256)
void zero_cnt_kernel()
{
    int i = blockIdx.x * 256 + threadIdx.x;
    if (i < N2) g_cnt[i] = 0;
}

__global__ __launch_bounds__(256)
void hist_both_kernel(const int* __restrict__ dst1, const int* __restrict__ dst2)
{
    int e = blockIdx.x * 256 + threadIdx.x;
    if (e < EE)            atomicAdd(&g_cnt[dst1[e]], 1);
    else if (e < 2 * EE)   atomicAdd(&g_cnt[NN + dst2[e - EE]], 1);
}

__global__ __launch_bounds__(SCAN_TB)
void scanA_kernel()
{
    __shared__ int s[SCAN_TB];
    int t = threadIdx.x;
    int i = blockIdx.x * SCAN_TB + t;
    int v = (i < N2) ? g_cnt[i] : 0;
    s[t] = v;
    __syncthreads();
    #pragma unroll
    for (int o = 1; o < SCAN_TB; o <<= 1) {
        int add = (t >= o) ? s[t - o] : 0;
        __syncthreads();
        s[t] += add;
        __syncthreads();
    }
    if (i < N2) g_off[i] = s[t] - v;
    if (t == SCAN_TB - 1) g_bsum[blockIdx.x] = s[SCAN_TB - 1];
}

__global__ __launch_bounds__(SCAN_TB)
void scanB_kernel()
{
    __shared__ int s[SCAN_TB];
    int t = threadIdx.x;
    int v = (t < NBA) ? g_bsum[t] : 0;
    s[t] = v;
    __syncthreads();
    #pragma unroll
    for (int o = 1; o < SCAN_TB; o <<= 1) {
        int add = (t >= o) ? s[t - o] : 0;
        __syncthreads();
        s[t] += add;
        __syncthreads();
    }
    g_bpre[t] = s[t] - v;
}

__global__ __launch_bounds__(256)
void scanC_kernel()
{
    int i = blockIdx.x * 256 + threadIdx.x;
    if (i < N2) {
        int o = g_off[i] + g_bpre[i / SCAN_TB];
        g_off[i] = o;
        g_pos[i] = o;
    }
    if (i == 0) g_off[N2] = 2 * EE;
}

__global__ __launch_bounds__(256)
void scatter_both_kernel(const int* __restrict__ src1, const int* __restrict__ dst1,
                         const int* __restrict__ src2, const int* __restrict__ dst2)
{
    int e = blockIdx.x * 256 + threadIdx.x;
    if (e < EE) {
        int p = atomicAdd(&g_pos[dst1[e]], 1);
        g_eidx[p] = src1[e];
    } else if (e < 2 * EE) {
        int p = atomicAdd(&g_pos[NN + dst2[e - EE]], 1);
        g_eidx[p] = src2[e - EE];
    }
}

// ---------------------------------------------------------------------------
// Node transform (layer 1 only): fs1 = h@Ws+bs ; fd1 = h@Wd+bd
// ---------------------------------------------------------------------------
__global__ __launch_bounds__(256)
void transform_kernel(const float* __restrict__ h,
                      const float* __restrict__ Wsrc, const float* __restrict__ bsrc,
                      const float* __restrict__ Wdst, const float* __restrict__ bdst)
{
    __shared__ float sWs[DD * DD], sWd[DD * DD], sbs[DD], sbd[DD];
    int t = threadIdx.x;
    if (t < DD * DD) { sWs[t] = Wsrc[t]; sWd[t] = Wdst[t]; }
    if (t < DD)      { sbs[t] = bsrc[t]; sbd[t] = bdst[t]; }
    __syncthreads();

    int i = blockIdx.x * 256 + t;
    if (i >= NN) return;

    float hr[DD];
    const float4* h4 = (const float4*)(h + (size_t)i * DD);
    #pragma unroll
    for (int q = 0; q < 4; q++) {
        float4 v = h4[q];
        hr[4*q+0] = v.x; hr[4*q+1] = v.y; hr[4*q+2] = v.z; hr[4*q+3] = v.w;
    }

    float4* fs4 = (float4*)(g_fs1 + (size_t)i * DD);
    float4* fd4 = (float4*)(g_fd1 + (size_t)i * DD);
    #pragma unroll
    for (int q = 0; q < 4; q++) {
        float as[4], ad[4];
        #pragma unroll
        for (int r = 0; r < 4; r++) {
            int j = 4*q + r;
            float a = sbs[j], b = sbd[j];
            #pragma unroll
            for (int k = 0; k < DD; k++) {
                a = fmaf(hr[k], sWs[k*DD + j], a);
                b = fmaf(hr[k], sWd[k*DD + j], b);
            }
            as[r] = a; ad[r] = b;
        }
        fs4[q] = make_float4(as[0], as[1], as[2], as[3]);
        fd4[q] = make_float4(ad[0], ad[1], ad[2], ad[3]);
    }
}

// ---------------------------------------------------------------------------
// Gather layer 1, fused with layer-2 transform.
// One warp per dst node; writes fs2/fd2 rows directly (no u2i round-trip).
// ---------------------------------------------------------------------------
__global__ __launch_bounds__(256)
void gather1_fused_kernel(const float* __restrict__ attn,
                          const float* __restrict__ Ws2, const float* __restrict__ bs2,
                          const float* __restrict__ Wd2, const float* __restrict__ bd2)
{
    __shared__ float sa[DD], sWs[DD * DD], sWd[DD * DD], sbs[DD], sbd[DD];
    int t = threadIdx.x;
    if (t < DD * DD) { sWs[t] = Ws2[t]; sWd[t] = Wd2[t]; }
    if (t < DD)      { sa[t] = attn[t]; sbs[t] = bs2[t]; sbd[t] = bd2[t]; }
    __syncthreads();

    int warp = blockIdx.x * 8 + (t >> 5);
    int lane = t & 31;
    if (warp >= NN) return;
    int d = warp;

    int beg = g_off[d], end = g_off[d + 1];

    float ed[DD];
    {
        const float4* fd4 = (const float4*)(g_fd1 + (size_t)d * DD);
        #pragma unroll
        for (int q = 0; q < 4; q++) {
            float4 v = fd4[q];
            ed[4*q+0] = v.x; ed[4*q+1] = v.y; ed[4*q+2] = v.z; ed[4*q+3] = v.w;
        }
    }

    float acc[DD];
    #pragma unroll
    for (int k = 0; k < DD; k++) acc[k] = 0.f;
    float den = 0.f;

    for (int base = beg; base < end; base += 32) {
        int e = base + lane;
        if (e < end) {
            int s = g_eidx[e];
            float el[DD];
            const float4* fs4 = (const float4*)(g_fs1 + (size_t)s * DD);
            #pragma unroll
            for (int q = 0; q < 4; q++) {
                float4 v = fs4[q];
                el[4*q+0] = v.x; el[4*q+1] = v.y; el[4*q+2] = v.z; el[4*q+3] = v.w;
            }
            float sc = 0.f;
            #pragma unroll
            for (int k = 0; k < DD; k++)
                sc = fmaf(lrelu(el[k] + ed[k], 0.2f), sa[k], sc);
            float ex = __expf(sc);
            den += ex;
            #pragma unroll
            for (int k = 0; k < DD; k++)
                acc[k] = fmaf(ex, el[k], acc[k]);
        }
    }

    #pragma unroll
    for (int o = 16; o > 0; o >>= 1) {
        #pragma unroll
        for (int k = 0; k < DD; k++)
            acc[k] += __shfl_xor_sync(0xFFFFFFFFu, acc[k], o);
        den += __shfl_xor_sync(0xFFFFFFFFu, den, o);
    }

    // layer-1 activation (replicated across lanes)
    float inv = (den > 0.f) ? (1.f / den) : 0.f;
    float row[DD];
    #pragma unroll
    for (int k = 0; k < DD; k++)
        row[k] = lrelu(acc[k] * inv, 0.01f);

    // fused layer-2 transform: lane j (< DD) computes output column j
    if (lane < DD) {
        float a = sbs[lane], b = sbd[lane];
        #pragma unroll
        for (int k = 0; k < DD; k++) {
            a = fmaf(row[k], sWs[k*DD + lane], a);
            b = fmaf(row[k], sWd[k*DD + lane], b);
        }
        g_fs2[(size_t)d * DD + lane] = a;
        g_fd2[(size_t)d * DD + lane] = b;
    }
}

// ---------------------------------------------------------------------------
// Gather layer 2 (final): writes the kernel output.
// ---------------------------------------------------------------------------
__global__ __launch_bounds__(256)
void gather2_kernel(const float* __restrict__ attn, float* __restrict__ out)
{
    __shared__ float sa[DD];
    int t = threadIdx.x;
    if (t < DD) sa[t] = attn[t];
    __syncthreads();

    int warp = blockIdx.x * 8 + (t >> 5);
    int lane = t & 31;
    if (warp >= NN) return;
    int d = warp;

    int beg = g_off[NN + d], end = g_off[NN + d + 1];

    float ed[DD];
    {
        const float4* fd4 = (const float4*)(g_fd2 + (size_t)d * DD);
        #pragma unroll
        for (int q = 0; q < 4; q++) {
            float4 v = fd4[q];
            ed[4*q+0] = v.x; ed[4*q+1] = v.y; ed[4*q+2] = v.z; ed[4*q+3] = v.w;
        }
    }

    float acc[DD];
    #pragma unroll
    for (int k = 0; k < DD; k++) acc[k] = 0.f;
    float den = 0.f;

    for (int base = beg; base < end; base += 32) {
        int e = base + lane;
        if (e < end) {
            int s = g_eidx[e];
            float el[DD];
            const float4* fs4 = (const float4*)(g_fs2 + (size_t)s * DD);
            #pragma unroll
            for (int q = 0; q < 4; q++) {
                float4 v = fs4[q];
                el[4*q+0] = v.x; el[4*q+1] = v.y; el[4*q+2] = v.z; el[4*q+3] = v.w;
            }
            float sc = 0.f;
            #pragma unroll
            for (int k = 0; k < DD; k++)
                sc = fmaf(lrelu(el[k] + ed[k], 0.2f), sa[k], sc);
            float ex = __expf(sc);
            den += ex;
            #pragma unroll
            for (int k = 0; k < DD; k++)
                acc[k] = fmaf(ex, el[k], acc[k]);
        }
    }

    #pragma unroll
    for (int o = 16; o > 0; o >>= 1) {
        #pragma unroll
        for (int k = 0; k < DD; k++)
            acc[k] += __shfl_xor_sync(0xFFFFFFFFu, acc[k], o);
        den += __shfl_xor_sync(0xFFFFFFFFu, den, o);
    }

    if (lane < 4) {
        float inv = (den > 0.f) ? (1.f / den) : 0.f;
        float4 o4;
        o4.x = lrelu(acc[4*lane+0] * inv, 0.01f);
        o4.y = lrelu(acc[4*lane+1] * inv, 0.01f);
        o4.z = lrelu(acc[4*lane+2] * inv, 0.01f);
        o4.w = lrelu(acc[4*lane+3] * inv, 0.01f);
        ((float4*)(out + (size_t)d * DD))[lane] = o4;
    }
}

// ---------------------------------------------------------------------------
extern "C" void kernel_launch(void* const* d_in, const int* in_sizes, int n_in,
                              void* d_out, int out_size)
{
    const float* emb  = (const float*)d_in[0];
    const int*   src1 = (const int*)  d_in[1];
    const int*   dst1 = (const int*)  d_in[2];
    const int*   src2 = (const int*)  d_in[3];
    const int*   dst2 = (const int*)  d_in[4];
    const float* Ws1  = (const float*)d_in[5];
    const float* bs1  = (const float*)d_in[6];
    const float* Wd1  = (const float*)d_in[7];
    const float* bd1  = (const float*)d_in[8];
    const float* at1  = (const float*)d_in[9];
    const float* Ws2  = (const float*)d_in[10];
    const float* bs2  = (const float*)d_in[11];
    const float* Wd2  = (const float*)d_in[12];
    const float* bd2  = (const float*)d_in[13];
    const float* at2  = (const float*)d_in[14];
    float* out = (float*)d_out;

    const int TB  = 256;
    const int gN2 = (N2 + TB - 1) / TB;
    const int gE2 = (2 * EE + TB - 1) / TB;
    const int gN  = (NN + TB - 1) / TB;
    const int gW  = (NN + 7) / 8;          // warp-per-node, 8 warps/block

    // CSR build for BOTH graphs (positions 1-6; #6 = scatter gets profiled)
    zero_cnt_kernel<<<gN2, TB>>>();
    hist_both_kernel<<<gE2, TB>>>(dst1, dst2);
    scanA_kernel<<<NBA, SCAN_TB>>>();
    scanB_kernel<<<1, SCAN_TB>>>();
    scanC_kernel<<<gN2, TB>>>();
    scatter_both_kernel<<<gE2, TB>>>(src1, dst1, src2, dst2);

    // Layer 1 transform + gather (fused with layer-2 transform)
    transform_kernel<<<gN, TB>>>(emb, Ws1, bs1, Wd1, bd1);
    gather1_fused_kernel<<<gW, TB>>>(at1, Ws2, bs2, Wd2, bd2);

    // Layer 2 gather -> output
    gather2_kernel<<<gW, TB>>>(at2, out);
}

// round 5
// speedup vs baseline: 1.1169x; 1.1169x over previous
#include <cuda_runtime.h>

#define NN 100000
#define DD 16
#define EE 3200000

// ---- scratch (device globals; .bss => zero at load) ----
__device__ float4 g_fs1[NN * 4];
__device__ float4 g_fd1[NN * 4];
__device__ float4 g_fs2[NN * 4];
__device__ float4 g_fd2[NN * 4];
__device__ float4 g_acc[NN * 4];   // invariant: all-zero at kernel_launch entry
__device__ float  g_den[NN];       // invariant: all-zero at kernel_launch entry

__device__ __forceinline__ float lrelu(float x, float s) {
    return fmaxf(x, s * x);        // valid for 0 < s < 1
}

// ---------------------------------------------------------------------------
// Layer-1 node transform: fs1 = h@Ws+bs ; fd1 = h@Wd+bd
// ---------------------------------------------------------------------------
__global__ __launch_bounds__(256)
void transform1_kernel(const float* __restrict__ h,
                       const float* __restrict__ Ws, const float* __restrict__ bs,
                       const float* __restrict__ Wd, const float* __restrict__ bd)
{
    __shared__ float sWs[DD * DD], sWd[DD * DD], sbs[DD], sbd[DD];
    int t = threadIdx.x;
    if (t < DD * DD) { sWs[t] = Ws[t]; sWd[t] = Wd[t]; }
    if (t < DD)      { sbs[t] = bs[t]; sbd[t] = bd[t]; }
    __syncthreads();

    int i = blockIdx.x * 256 + t;
    if (i >= NN) return;

    float hr[DD];
    const float4* h4 = (const float4*)(h + (size_t)i * DD);
    #pragma unroll
    for (int q = 0; q < 4; q++) {
        float4 v = h4[q];
        hr[4*q+0] = v.x; hr[4*q+1] = v.y; hr[4*q+2] = v.z; hr[4*q+3] = v.w;
    }

    #pragma unroll
    for (int q = 0; q < 4; q++) {
        float as[4], ad[4];
        #pragma unroll
        for (int r = 0; r < 4; r++) {
            int j = 4*q + r;
            float a = sbs[j], b = sbd[j];
            #pragma unroll
            for (int k = 0; k < DD; k++) {
                a = fmaf(hr[k], sWs[k*DD + j], a);
                b = fmaf(hr[k], sWd[k*DD + j], b);
            }
            as[r] = a; ad[r] = b;
        }
        g_fs1[(size_t)i * 4 + q] = make_float4(as[0], as[1], as[2], as[3]);
        g_fd1[(size_t)i * 4 + q] = make_float4(ad[0], ad[1], ad[2], ad[3]);
    }
}

// ---------------------------------------------------------------------------
// Single-pass edge kernel: score -> exp -> vector reduction into acc/den.
// (No max-subtraction: scores are O(10), exp fp32-safe; validated R2-R4.)
// ---------------------------------------------------------------------------
__global__ __launch_bounds__(256)
void edge_kernel(const int* __restrict__ src, const int* __restrict__ dst,
                 const float* __restrict__ attn,
                 const float4* __restrict__ fs, const float4* __restrict__ fd)
{
    __shared__ float sa[DD];
    if (threadIdx.x < DD) sa[threadIdx.x] = attn[threadIdx.x];
    __syncthreads();

    int e = blockIdx.x * 256 + threadIdx.x;
    if (e >= EE) return;

    int s = src[e], d = dst[e];

    float4 A0 = fs[(size_t)s*4+0], A1 = fs[(size_t)s*4+1],
           A2 = fs[(size_t)s*4+2], A3 = fs[(size_t)s*4+3];
    float4 B0 = fd[(size_t)d*4+0], B1 = fd[(size_t)d*4+1],
           B2 = fd[(size_t)d*4+2], B3 = fd[(size_t)d*4+3];

    float sc = 0.f;
    sc = fmaf(lrelu(A0.x + B0.x, 0.2f), sa[ 0], sc);
    sc = fmaf(lrelu(A0.y + B0.y, 0.2f), sa[ 1], sc);
    sc = fmaf(lrelu(A0.z + B0.z, 0.2f), sa[ 2], sc);
    sc = fmaf(lrelu(A0.w + B0.w, 0.2f), sa[ 3], sc);
    sc = fmaf(lrelu(A1.x + B1.x, 0.2f), sa[ 4], sc);
    sc = fmaf(lrelu(A1.y + B1.y, 0.2f), sa[ 5], sc);
    sc = fmaf(lrelu(A1.z + B1.z, 0.2f), sa[ 6], sc);
    sc = fmaf(lrelu(A1.w + B1.w, 0.2f), sa[ 7], sc);
    sc = fmaf(lrelu(A2.x + B2.x, 0.2f), sa[ 8], sc);
    sc = fmaf(lrelu(A2.y + B2.y, 0.2f), sa[ 9], sc);
    sc = fmaf(lrelu(A2.z + B2.z, 0.2f), sa[10], sc);
    sc = fmaf(lrelu(A2.w + B2.w, 0.2f), sa[11], sc);
    sc = fmaf(lrelu(A3.x + B3.x, 0.2f), sa[12], sc);
    sc = fmaf(lrelu(A3.y + B3.y, 0.2f), sa[13], sc);
    sc = fmaf(lrelu(A3.z + B3.z, 0.2f), sa[14], sc);
    sc = fmaf(lrelu(A3.w + B3.w, 0.2f), sa[15], sc);

    float ex = __expf(sc);

    float4* ab = &g_acc[(size_t)d * 4];
    asm volatile("red.global.add.v4.f32 [%0], {%1, %2, %3, %4};"
                 :: "l"(ab + 0), "f"(ex*A0.x), "f"(ex*A0.y), "f"(ex*A0.z), "f"(ex*A0.w) : "memory");
    asm volatile("red.global.add.v4.f32 [%0], {%1, %2, %3, %4};"
                 :: "l"(ab + 1), "f"(ex*A1.x), "f"(ex*A1.y), "f"(ex*A1.z), "f"(ex*A1.w) : "memory");
    asm volatile("red.global.add.v4.f32 [%0], {%1, %2, %3, %4};"
                 :: "l"(ab + 2), "f"(ex*A2.x), "f"(ex*A2.y), "f"(ex*A2.z), "f"(ex*A2.w) : "memory");
    asm volatile("red.global.add.v4.f32 [%0], {%1, %2, %3, %4};"
                 :: "l"(ab + 3), "f"(ex*A3.x), "f"(ex*A3.y), "f"(ex*A3.z), "f"(ex*A3.w) : "memory");
    asm volatile("red.global.add.f32 [%0], %1;"
                 :: "l"(&g_den[d]), "f"(ex) : "memory");
}

// ---------------------------------------------------------------------------
// Finalize layer 1 + fused layer-2 transform. Re-zeros acc/den in place.
// ---------------------------------------------------------------------------
__global__ __launch_bounds__(256)
void finalize1_kernel(const float* __restrict__ Ws2, const float* __restrict__ bs2,
                      const float* __restrict__ Wd2, const float* __restrict__ bd2)
{
    __shared__ float sWs[DD * DD], sWd[DD * DD], sbs[DD], sbd[DD];
    int t = threadIdx.x;
    if (t < DD * DD) { sWs[t] = Ws2[t]; sWd[t] = Wd2[t]; }
    if (t < DD)      { sbs[t] = bs2[t]; sbd[t] = bd2[t]; }
    __syncthreads();

    int i = blockIdx.x * 256 + t;
    if (i >= NN) return;

    float den = g_den[i];
    g_den[i] = 0.f;
    float inv = (den > 0.f) ? (1.f / den) : 0.f;

    float row[DD];
    const float4 z4 = make_float4(0.f, 0.f, 0.f, 0.f);
    #pragma unroll
    for (int q = 0; q < 4; q++) {
        float4 v = g_acc[(size_t)i * 4 + q];
        g_acc[(size_t)i * 4 + q] = z4;
        row[4*q+0] = lrelu(v.x * inv, 0.01f);
        row[4*q+1] = lrelu(v.y * inv, 0.01f);
        row[4*q+2] = lrelu(v.z * inv, 0.01f);
        row[4*q+3] = lrelu(v.w * inv, 0.01f);
    }

    #pragma unroll
    for (int q = 0; q < 4; q++) {
        float as[4], ad[4];
        #pragma unroll
        for (int r = 0; r < 4; r++) {
            int j = 4*q + r;
            float a = sbs[j], b = sbd[j];
            #pragma unroll
            for (int k = 0; k < DD; k++) {
                a = fmaf(row[k], sWs[k*DD + j], a);
                b = fmaf(row[k], sWd[k*DD + j], b);
            }
            as[r] = a; ad[r] = b;
        }
        g_fs2[(size_t)i * 4 + q] = make_float4(as[0], as[1], as[2], as[3]);
        g_fd2[(size_t)i * 4 + q] = make_float4(ad[0], ad[1], ad[2], ad[3]);
    }
}

// ---------------------------------------------------------------------------
// Finalize layer 2 -> output. Re-zeros acc/den (restores invariant).
// ---------------------------------------------------------------------------
__global__ __launch_bounds__(256)
void finalize2_kernel(float* __restrict__ out)
{
    int i = blockIdx.x * 256 + threadIdx.x;
    if (i >= NN) return;

    float den = g_den[i];
    g_den[i] = 0.f;
    float inv = (den > 0.f) ? (1.f / den) : 0.f;

    const float4 z4 = make_float4(0.f, 0.f, 0.f, 0.f);
    float4* o4 = (float4*)(out + (size_t)i * DD);
    #pragma unroll
    for (int q = 0; q < 4; q++) {
        float4 v = g_acc[(size_t)i * 4 + q];
        g_acc[(size_t)i * 4 + q] = z4;
        float4 r;
        r.x = lrelu(v.x * inv, 0.01f);
        r.y = lrelu(v.y * inv, 0.01f);
        r.z = lrelu(v.z * inv, 0.01f);
        r.w = lrelu(v.w * inv, 0.01f);
        o4[q] = r;
    }
}

// ---------------------------------------------------------------------------
extern "C" void kernel_launch(void* const* d_in, const int* in_sizes, int n_in,
                              void* d_out, int out_size)
{
    const float* emb  = (const float*)d_in[0];
    const int*   src1 = (const int*)  d_in[1];
    const int*   dst1 = (const int*)  d_in[2];
    const int*   src2 = (const int*)  d_in[3];
    const int*   dst2 = (const int*)  d_in[4];
    const float* Ws1  = (const float*)d_in[5];
    const float* bs1  = (const float*)d_in[6];
    const float* Wd1  = (const float*)d_in[7];
    const float* bd1  = (const float*)d_in[8];
    const float* at1  = (const float*)d_in[9];
    const float* Ws2  = (const float*)d_in[10];
    const float* bs2  = (const float*)d_in[11];
    const float* Wd2  = (const float*)d_in[12];
    const float* bd2  = (const float*)d_in[13];
    const float* at2  = (const float*)d_in[14];
    float* out = (float*)d_out;

    float4 *p_fs1, *p_fd1, *p_fs2, *p_fd2;
    cudaGetSymbolAddress((void**)&p_fs1, g_fs1);
    cudaGetSymbolAddress((void**)&p_fd1, g_fd1);
    cudaGetSymbolAddress((void**)&p_fs2, g_fs2);
    cudaGetSymbolAddress((void**)&p_fd2, g_fd2);

    const int TB = 256;
    const int gN = (NN + TB - 1) / TB;
    const int gE = (EE + TB - 1) / TB;

    transform1_kernel<<<gN, TB>>>(emb, Ws1, bs1, Wd1, bd1);
    edge_kernel<<<gE, TB>>>(src1, dst1, at1, p_fs1, p_fd1);
    finalize1_kernel<<<gN, TB>>>(Ws2, bs2, Wd2, bd2);
    edge_kernel<<<gE, TB>>>(src2, dst2, at2, p_fs2, p_fd2);
    finalize2_kernel<<<gN, TB>>>(out);
}

// round 6
// speedup vs baseline: 1.7836x; 1.5970x over previous
#include <cuda_runtime.h>

#define NN 100000
#define DD 16
#define EE 3200000

// ---- scratch (device globals; .bss => zero at load) ----
__device__ float4 g_fs1[NN * 4];
__device__ float4 g_fd1[NN * 4];
__device__ float4 g_fs2[NN * 4];
__device__ float4 g_fd2[NN * 4];
__device__ float4 g_acc[NN * 4];   // invariant: all-zero at kernel_launch entry
__device__ float  g_den[NN];       // invariant: all-zero at kernel_launch entry

__device__ __forceinline__ float lrelu(float x, float s) {
    return fmaxf(x, s * x);        // valid for 0 < s < 1
}

// ---------------------------------------------------------------------------
// Layer-1 node transform: fs1 = h@Ws+bs ; fd1 = h@Wd+bd
// ---------------------------------------------------------------------------
__global__ __launch_bounds__(256)
void transform1_kernel(const float* __restrict__ h,
                       const float* __restrict__ Ws, const float* __restrict__ bs,
                       const float* __restrict__ Wd, const float* __restrict__ bd)
{
    __shared__ float sWs[DD * DD], sWd[DD * DD], sbs[DD], sbd[DD];
    int t = threadIdx.x;
    if (t < DD * DD) { sWs[t] = Ws[t]; sWd[t] = Wd[t]; }
    if (t < DD)      { sbs[t] = bs[t]; sbd[t] = bd[t]; }
    __syncthreads();

    int i = blockIdx.x * 256 + t;
    if (i >= NN) return;

    float hr[DD];
    const float4* h4 = (const float4*)(h + (size_t)i * DD);
    #pragma unroll
    for (int q = 0; q < 4; q++) {
        float4 v = h4[q];
        hr[4*q+0] = v.x; hr[4*q+1] = v.y; hr[4*q+2] = v.z; hr[4*q+3] = v.w;
    }

    #pragma unroll
    for (int q = 0; q < 4; q++) {
        float as[4], ad[4];
        #pragma unroll
        for (int r = 0; r < 4; r++) {
            int j = 4*q + r;
            float a = sbs[j], b = sbd[j];
            #pragma unroll
            for (int k = 0; k < DD; k++) {
                a = fmaf(hr[k], sWs[k*DD + j], a);
                b = fmaf(hr[k], sWd[k*DD + j], b);
            }
            as[r] = a; ad[r] = b;
        }
        g_fs1[(size_t)i * 4 + q] = make_float4(as[0], as[1], as[2], as[3]);
        g_fd1[(size_t)i * 4 + q] = make_float4(ad[0], ad[1], ad[2], ad[3]);
    }
}

// ---------------------------------------------------------------------------
// Quad-per-edge kernel: 4 lanes cooperate on one edge.
// Lane q owns float4 part q of the 64B feature rows, so each LDG.128 /
// red.v4 touches only 8 distinct 128B lines per warp (1 wavefront/edge).
// ---------------------------------------------------------------------------
__global__ __launch_bounds__(256)
void edge_kernel(const int* __restrict__ src, const int* __restrict__ dst,
                 const float* __restrict__ attn,
                 const float4* __restrict__ fs, const float4* __restrict__ fd)
{
    __shared__ float sa[DD];
    if (threadIdx.x < DD) sa[threadIdx.x] = attn[threadIdx.x];
    __syncthreads();

    int tid = blockIdx.x * 256 + threadIdx.x;
    int e = tid >> 2;            // edge index (4 lanes per edge)
    int q = threadIdx.x & 3;     // float4 part within the 16-vector
    if (e >= EE) return;

    // attn components for this lane's quad part
    float a0 = sa[4*q+0], a1 = sa[4*q+1], a2 = sa[4*q+2], a3 = sa[4*q+3];

    int s = __ldg(&src[e]);
    int d = __ldg(&dst[e]);

    float4 A = fs[(size_t)s * 4 + q];
    float4 B = fd[(size_t)d * 4 + q];

    // partial score over this lane's 4 components
    float p;
    p = lrelu(A.x + B.x, 0.2f) * a0;
    p = fmaf(lrelu(A.y + B.y, 0.2f), a1, p);
    p = fmaf(lrelu(A.z + B.z, 0.2f), a2, p);
    p = fmaf(lrelu(A.w + B.w, 0.2f), a3, p);

    // intra-quad reduce -> all 4 lanes hold the full score
    p += __shfl_xor_sync(0xFFFFFFFFu, p, 1);
    p += __shfl_xor_sync(0xFFFFFFFFu, p, 2);

    float ex = __expf(p);

    float4* ab = &g_acc[(size_t)d * 4 + q];
    asm volatile("red.global.add.v4.f32 [%0], {%1, %2, %3, %4};"
                 :: "l"(ab), "f"(ex*A.x), "f"(ex*A.y), "f"(ex*A.z), "f"(ex*A.w)
                 : "memory");
    if (q == 0)
        asm volatile("red.global.add.f32 [%0], %1;"
                     :: "l"(&g_den[d]), "f"(ex) : "memory");
}

// ---------------------------------------------------------------------------
// Finalize layer 1 + fused layer-2 transform. Re-zeros acc/den in place.
// ---------------------------------------------------------------------------
__global__ __launch_bounds__(256)
void finalize1_kernel(const float* __restrict__ Ws2, const float* __restrict__ bs2,
                      const float* __restrict__ Wd2, const float* __restrict__ bd2)
{
    __shared__ float sWs[DD * DD], sWd[DD * DD], sbs[DD], sbd[DD];
    int t = threadIdx.x;
    if (t < DD * DD) { sWs[t] = Ws2[t]; sWd[t] = Wd2[t]; }
    if (t < DD)      { sbs[t] = bs2[t]; sbd[t] = bd2[t]; }
    __syncthreads();

    int i = blockIdx.x * 256 + t;
    if (i >= NN) return;

    float den = g_den[i];
    g_den[i] = 0.f;
    float inv = (den > 0.f) ? (1.f / den) : 0.f;

    float row[DD];
    const float4 z4 = make_float4(0.f, 0.f, 0.f, 0.f);
    #pragma unroll
    for (int q = 0; q < 4; q++) {
        float4 v = g_acc[(size_t)i * 4 + q];
        g_acc[(size_t)i * 4 + q] = z4;
        row[4*q+0] = lrelu(v.x * inv, 0.01f);
        row[4*q+1] = lrelu(v.y * inv, 0.01f);
        row[4*q+2] = lrelu(v.z * inv, 0.01f);
        row[4*q+3] = lrelu(v.w * inv, 0.01f);
    }

    #pragma unroll
    for (int q = 0; q < 4; q++) {
        float as[4], ad[4];
        #pragma unroll
        for (int r = 0; r < 4; r++) {
            int j = 4*q + r;
            float a = sbs[j], b = sbd[j];
            #pragma unroll
            for (int k = 0; k < DD; k++) {
                a = fmaf(row[k], sWs[k*DD + j], a);
                b = fmaf(row[k], sWd[k*DD + j], b);
            }
            as[r] = a; ad[r] = b;
        }
        g_fs2[(size_t)i * 4 + q] = make_float4(as[0], as[1], as[2], as[3]);
        g_fd2[(size_t)i * 4 + q] = make_float4(ad[0], ad[1], ad[2], ad[3]);
    }
}

// ---------------------------------------------------------------------------
// Finalize layer 2 -> output. Re-zeros acc/den (restores invariant).
// ---------------------------------------------------------------------------
__global__ __launch_bounds__(256)
void finalize2_kernel(float* __restrict__ out)
{
    int i = blockIdx.x * 256 + threadIdx.x;
    if (i >= NN) return;

    float den = g_den[i];
    g_den[i] = 0.f;
    float inv = (den > 0.f) ? (1.f / den) : 0.f;

    const float4 z4 = make_float4(0.f, 0.f, 0.f, 0.f);
    float4* o4 = (float4*)(out + (size_t)i * DD);
    #pragma unroll
    for (int q = 0; q < 4; q++) {
        float4 v = g_acc[(size_t)i * 4 + q];
        g_acc[(size_t)i * 4 + q] = z4;
        float4 r;
        r.x = lrelu(v.x * inv, 0.01f);
        r.y = lrelu(v.y * inv, 0.01f);
        r.z = lrelu(v.z * inv, 0.01f);
        r.w = lrelu(v.w * inv, 0.01f);
        o4[q] = r;
    }
}

// ---------------------------------------------------------------------------
extern "C" void kernel_launch(void* const* d_in, const int* in_sizes, int n_in,
                              void* d_out, int out_size)
{
    const float* emb  = (const float*)d_in[0];
    const int*   src1 = (const int*)  d_in[1];
    const int*   dst1 = (const int*)  d_in[2];
    const int*   src2 = (const int*)  d_in[3];
    const int*   dst2 = (const int*)  d_in[4];
    const float* Ws1  = (const float*)d_in[5];
    const float* bs1  = (const float*)d_in[6];
    const float* Wd1  = (const float*)d_in[7];
    const float* bd1  = (const float*)d_in[8];
    const float* at1  = (const float*)d_in[9];
    const float* Ws2  = (const float*)d_in[10];
    const float* bs2  = (const float*)d_in[11];
    const float* Wd2  = (const float*)d_in[12];
    const float* bd2  = (const float*)d_in[13];
    const float* at2  = (const float*)d_in[14];
    float* out = (float*)d_out;

    float4 *p_fs1, *p_fd1, *p_fs2, *p_fd2;
    cudaGetSymbolAddress((void**)&p_fs1, g_fs1);
    cudaGetSymbolAddress((void**)&p_fd1, g_fd1);
    cudaGetSymbolAddress((void**)&p_fs2, g_fs2);
    cudaGetSymbolAddress((void**)&p_fd2, g_fd2);

    const int TB = 256;
    const int gN = (NN + TB - 1) / TB;
    const int gE = (EE * 4 + TB - 1) / TB;   // 4 lanes per edge

    transform1_kernel<<<gN, TB>>>(emb, Ws1, bs1, Wd1, bd1);
    edge_kernel<<<gE, TB>>>(src1, dst1, at1, p_fs1, p_fd1);
    finalize1_kernel<<<gN, TB>>>(Ws2, bs2, Wd2, bd2);
    edge_kernel<<<gE, TB>>>(src2, dst2, at2, p_fs2, p_fd2);
    finalize2_kernel<<<gN, TB>>>(out);
}